// round 1
// baseline (speedup 1.0000x reference)
#include <cuda_runtime.h>

// Problem shape (fixed by the dataset)
constexpr int NA = 1024;   // rows of a
constexpr int NB = 1024;   // rows of b
constexpr int DD = 512;    // feature dim (reduction of stage 1)
constexpr int KK = 256;    // number of feats (reduction of stage 2)

// GEMM tiling
constexpr int BM = 64, BN = 64, BK = 16;

// Scratch (no cudaMalloc allowed): P = relu(a@featsT), M = (b@featsT <= 0)
__device__ float g_P[NA * KK];
__device__ float g_M[NB * KK];

// ---------------------------------------------------------------------------
// Stage 1: NT GEMM over stacked [a; b] (2048 x 512) vs feats (256 x 512).
// Epilogue writes P (relu) for the first 1024 rows, M (0/1 mask) for the rest.
// ---------------------------------------------------------------------------
__global__ __launch_bounds__(256) void fk_kernel(
    const float* __restrict__ a,
    const float* __restrict__ b,
    const float* __restrict__ feats)
{
    __shared__ float Xs[BK][BM + 4];   // [d][m], padded row stride 68 (16B-aligned)
    __shared__ float Fs[BK][BN + 4];   // [d][n]

    const int tid = threadIdx.x;
    const int m0  = blockIdx.y * BM;   // 0..2047 (tile-aligned to the a/b boundary)
    const int n0  = blockIdx.x * BN;   // 0..255

    const bool isA = (m0 < NA);
    const float* __restrict__ X = isA ? a : b;
    float* __restrict__ Out     = isA ? g_P : g_M;
    const int mbase = isA ? m0 : (m0 - NA);

    const int lr = tid >> 2;           // 0..63  : row within tile
    const int lc = (tid & 3) << 2;     // 0,4,8,12: d-offset within BK

    const int ty = tid >> 4;           // 0..15
    const int tx = tid & 15;           // 0..15

    float acc[4][4] = {};

    for (int d0 = 0; d0 < DD; d0 += BK) {
        float4 xv = *reinterpret_cast<const float4*>(&X[(mbase + lr) * DD + d0 + lc]);
        float4 fv = *reinterpret_cast<const float4*>(&feats[(n0 + lr) * DD + d0 + lc]);
        Xs[lc + 0][lr] = xv.x; Xs[lc + 1][lr] = xv.y;
        Xs[lc + 2][lr] = xv.z; Xs[lc + 3][lr] = xv.w;
        Fs[lc + 0][lr] = fv.x; Fs[lc + 1][lr] = fv.y;
        Fs[lc + 2][lr] = fv.z; Fs[lc + 3][lr] = fv.w;
        __syncthreads();

        #pragma unroll
        for (int k = 0; k < BK; k++) {
            float4 xr = *reinterpret_cast<const float4*>(&Xs[k][ty << 2]);
            float4 fr = *reinterpret_cast<const float4*>(&Fs[k][tx << 2]);
            float xa[4] = {xr.x, xr.y, xr.z, xr.w};
            float fa[4] = {fr.x, fr.y, fr.z, fr.w};
            #pragma unroll
            for (int i = 0; i < 4; i++)
                #pragma unroll
                for (int j = 0; j < 4; j++)
                    acc[i][j] = fmaf(xa[i], fa[j], acc[i][j]);
        }
        __syncthreads();
    }

    // Epilogue: P = max(v,0); M = (v <= 0) ? 1 : 0
    #pragma unroll
    for (int i = 0; i < 4; i++) {
        const int r = mbase + (ty << 2) + i;
        float4 o;
        float* oc = &o.x;
        #pragma unroll
        for (int j = 0; j < 4; j++) {
            float v = acc[i][j];
            oc[j] = isA ? fmaxf(v, 0.0f) : ((v <= 0.0f) ? 1.0f : 0.0f);
        }
        *reinterpret_cast<float4*>(&Out[r * KK + n0 + (tx << 2)]) = o;
    }
}

// ---------------------------------------------------------------------------
// Stage 2: result = P @ M^T   (1024 x 1024, reduce K=256)
// ---------------------------------------------------------------------------
__global__ __launch_bounds__(256) void big_kernel(float* __restrict__ out)
{
    __shared__ float Ps[BK][BM + 4];
    __shared__ float Ms[BK][BN + 4];

    const int tid = threadIdx.x;
    const int i0  = blockIdx.y * BM;
    const int j0  = blockIdx.x * BN;

    const int lr = tid >> 2;
    const int lc = (tid & 3) << 2;
    const int ty = tid >> 4;
    const int tx = tid & 15;

    float acc[4][4] = {};

    for (int k0 = 0; k0 < KK; k0 += BK) {
        float4 pv = *reinterpret_cast<const float4*>(&g_P[(i0 + lr) * KK + k0 + lc]);
        float4 mv = *reinterpret_cast<const float4*>(&g_M[(j0 + lr) * KK + k0 + lc]);
        Ps[lc + 0][lr] = pv.x; Ps[lc + 1][lr] = pv.y;
        Ps[lc + 2][lr] = pv.z; Ps[lc + 3][lr] = pv.w;
        Ms[lc + 0][lr] = mv.x; Ms[lc + 1][lr] = mv.y;
        Ms[lc + 2][lr] = mv.z; Ms[lc + 3][lr] = mv.w;
        __syncthreads();

        #pragma unroll
        for (int k = 0; k < BK; k++) {
            float4 pr = *reinterpret_cast<const float4*>(&Ps[k][ty << 2]);
            float4 mr = *reinterpret_cast<const float4*>(&Ms[k][tx << 2]);
            float pa[4] = {pr.x, pr.y, pr.z, pr.w};
            float ma[4] = {mr.x, mr.y, mr.z, mr.w};
            #pragma unroll
            for (int i = 0; i < 4; i++)
                #pragma unroll
                for (int j = 0; j < 4; j++)
                    acc[i][j] = fmaf(pa[i], ma[j], acc[i][j]);
        }
        __syncthreads();
    }

    #pragma unroll
    for (int i = 0; i < 4; i++) {
        const int r = i0 + (ty << 2) + i;
        float4 o = make_float4(acc[i][0], acc[i][1], acc[i][2], acc[i][3]);
        *reinterpret_cast<float4*>(&out[r * NB + j0 + (tx << 2)]) = o;
    }
}

// ---------------------------------------------------------------------------
extern "C" void kernel_launch(void* const* d_in, const int* in_sizes, int n_in,
                              void* d_out, int out_size)
{
    const float* a     = (const float*)d_in[0];   // (1024, 512)
    const float* b     = (const float*)d_in[1];   // (1024, 512)
    const float* feats = (const float*)d_in[2];   // (256, 512)
    float* out = (float*)d_out;                   // (1024, 1024)

    (void)in_sizes; (void)n_in; (void)out_size;

    dim3 gA(KK / BN, (NA + NB) / BM);   // (4, 32) = 128 blocks
    fk_kernel<<<gA, 256>>>(a, b, feats);

    dim3 gB(NB / BN, NA / BM);          // (16, 16) = 256 blocks
    big_kernel<<<gB, 256>>>(out);
}

// round 3
// speedup vs baseline: 1.5524x; 1.5524x over previous
#include <cuda_runtime.h>
#include <cuda_bf16.h>
#include <cstdint>

constexpr int NA = 1024, NB = 1024, DD = 512, KK = 256;
constexpr int XROWS = NA + NB;

// Device scratch
__device__ __nv_bfloat16 g_Xh[XROWS * DD];
__device__ __nv_bfloat16 g_Xl[XROWS * DD];
__device__ __nv_bfloat16 g_Fh[KK * DD];
__device__ __nv_bfloat16 g_Fl[KK * DD];
__device__ __nv_bfloat16 g_Ph[NA * KK];
__device__ __nv_bfloat16 g_Pl[NA * KK];
__device__ __nv_bfloat16 g_Mb[NB * KK];

// ---------------------------------------------------------------------------
// PTX helpers (sm_80+ family-safe: cp.async, ldmatrix, mma.sync bf16)
// ---------------------------------------------------------------------------
__device__ __forceinline__ uint32_t smem_u32(const void* p) {
    uint32_t r;
    asm("{ .reg .u64 t; cvta.to.shared.u64 t, %1; cvt.u32.u64 %0, t; }" : "=r"(r) : "l"(p));
    return r;
}
__device__ __forceinline__ void cp16(uint32_t dst, const void* src) {
    asm volatile("cp.async.cg.shared.global [%0], [%1], 16;" :: "r"(dst), "l"(src) : "memory");
}
__device__ __forceinline__ void cp_commit() { asm volatile("cp.async.commit_group;" ::: "memory"); }
__device__ __forceinline__ void cp_wait1()  { asm volatile("cp.async.wait_group 1;" ::: "memory"); }
__device__ __forceinline__ void cp_wait0()  { asm volatile("cp.async.wait_group 0;" ::: "memory"); }

__device__ __forceinline__ void ldm_x4(uint32_t* r, uint32_t addr) {
    asm volatile("ldmatrix.sync.aligned.m8n8.x4.shared.b16 {%0,%1,%2,%3}, [%4];"
                 : "=r"(r[0]), "=r"(r[1]), "=r"(r[2]), "=r"(r[3]) : "r"(addr));
}
__device__ __forceinline__ void mma_bf16(float* d, const uint32_t* a, const uint32_t* b) {
    asm volatile(
        "mma.sync.aligned.m16n8k16.row.col.f32.bf16.bf16.f32 "
        "{%0,%1,%2,%3}, {%4,%5,%6,%7}, {%8,%9}, {%0,%1,%2,%3};"
        : "+f"(d[0]), "+f"(d[1]), "+f"(d[2]), "+f"(d[3])
        : "r"(a[0]), "r"(a[1]), "r"(a[2]), "r"(a[3]), "r"(b[0]), "r"(b[1]));
}

// smem tile geometry: k-chunk 32 bf16 per row = 64B data, padded to 80B rows
constexpr uint32_t RSTRIDE = 80;

// ldmatrix address for one m16k16 A-tile (row0 = tile top row in smem tile)
__device__ __forceinline__ uint32_t a_addr(uint32_t base, int row0, int lane, int koff) {
    return base + (uint32_t)(row0 + (lane & 15)) * RSTRIDE + (uint32_t)koff + ((lane >> 4) << 4);
}
// ldmatrix address for two stacked n8k16 B-tiles (16 rows)
__device__ __forceinline__ uint32_t b_addr(uint32_t base, int row0, int lane, int koff) {
    return base + (uint32_t)(row0 + (lane & 7) + ((lane >> 4) << 3)) * RSTRIDE
                + (uint32_t)koff + (((lane >> 3) & 1) << 4);
}

// cp.async loader: rows x 32 bf16 chunk from (src + row*ld + d0)
__device__ __forceinline__ void load_tile(uint32_t dst, const __nv_bfloat16* __restrict__ src,
                                          int rows, int ld, int d0, int tid)
{
    int n = rows * 4;   // 4 x 16B per row
    for (int v = tid; v < n; v += 256) {
        int r = v >> 2, s = v & 3;
        cp16(dst + (uint32_t)r * RSTRIDE + (uint32_t)(s << 4),
             src + (size_t)r * ld + d0 + s * 8);
    }
}

// ---------------------------------------------------------------------------
// Kernel 0: split fp32 -> (hi, lo) bf16
// ---------------------------------------------------------------------------
__global__ __launch_bounds__(256) void convert_kernel(
    const float* __restrict__ a, const float* __restrict__ b, const float* __restrict__ feats)
{
    constexpr int XN4 = XROWS * DD / 4;
    constexpr int FN4 = KK * DD / 4;
    int i4 = blockIdx.x * 256 + threadIdx.x;
    if (i4 >= XN4 + FN4) return;

    float4 v;
    __nv_bfloat16 *H, *L;
    int base;
    if (i4 < XN4) {
        base = i4 * 4;
        v = (base < NA * DD) ? *reinterpret_cast<const float4*>(a + base)
                             : *reinterpret_cast<const float4*>(b + base - NA * DD);
        H = g_Xh; L = g_Xl;
    } else {
        base = (i4 - XN4) * 4;
        v = *reinterpret_cast<const float4*>(feats + base);
        H = g_Fh; L = g_Fl;
    }
    float xs[4] = {v.x, v.y, v.z, v.w};
    __nv_bfloat16 hs[4], ls[4];
#pragma unroll
    for (int i = 0; i < 4; i++) {
        hs[i] = __float2bfloat16(xs[i]);
        ls[i] = __float2bfloat16(xs[i] - __bfloat162float(hs[i]));
    }
    *reinterpret_cast<__nv_bfloat162*>(H + base)     = __nv_bfloat162(hs[0], hs[1]);
    *reinterpret_cast<__nv_bfloat162*>(H + base + 2) = __nv_bfloat162(hs[2], hs[3]);
    *reinterpret_cast<__nv_bfloat162*>(L + base)     = __nv_bfloat162(ls[0], ls[1]);
    *reinterpret_cast<__nv_bfloat162*>(L + base + 2) = __nv_bfloat162(ls[2], ls[3]);
}

// ---------------------------------------------------------------------------
// Stage 1: C[2048x256] = X · F^T  (AhFh + AhFl + AlFh), tile 128x64
// grid (4, 16), 256 threads. Epilogue -> Ph/Pl (relu split) or Mb (mask).
// ---------------------------------------------------------------------------
constexpr uint32_t S1_AH = 0;
constexpr uint32_t S1_AL = 10240;
constexpr uint32_t S1_FH = 20480;
constexpr uint32_t S1_FL = 25600;
constexpr uint32_t S1_BUF = 30720;
constexpr int S1_SMEM = 61440;

__global__ __launch_bounds__(256) void stage1_mma()
{
    extern __shared__ char dsm[];
    const uint32_t sb = smem_u32(dsm);

    const int tid = threadIdx.x;
    const int lane = tid & 31;
    const int wid = tid >> 5;
    const int wm = wid & 3;          // 4 warp rows x 32
    const int wn = wid >> 2;         // 2 warp cols x 32

    const int m0 = blockIdx.y * 128;
    const int n0 = blockIdx.x * 64;
    const __nv_bfloat16* Ah = g_Xh + (size_t)m0 * DD;
    const __nv_bfloat16* Al = g_Xl + (size_t)m0 * DD;
    const __nv_bfloat16* Fh = g_Fh + (size_t)n0 * DD;
    const __nv_bfloat16* Fl = g_Fl + (size_t)n0 * DD;

    float acc[2][4][4] = {};

    auto load_chunk = [&](int ch, uint32_t bb) {
        const int d0 = ch * 32;
        load_tile(bb + S1_AH, Ah, 128, DD, d0, tid);
        load_tile(bb + S1_AL, Al, 128, DD, d0, tid);
        load_tile(bb + S1_FH, Fh,  64, DD, d0, tid);
        load_tile(bb + S1_FL, Fl,  64, DD, d0, tid);
        cp_commit();
    };

    constexpr int NCH = DD / 32;   // 16
    load_chunk(0, sb);
    for (int ch = 0; ch < NCH; ch++) {
        const bool more = (ch + 1 < NCH);
        if (more) load_chunk(ch + 1, sb + ((ch + 1) & 1) * S1_BUF);
        if (more) cp_wait1(); else cp_wait0();
        __syncthreads();

        const uint32_t bb = sb + (ch & 1) * S1_BUF;
#pragma unroll
        for (int ks = 0; ks < 2; ks++) {
            const int koff = ks * 32;
            uint32_t ah[2][4], al[2][4], fh[2][4], fl[2][4];
#pragma unroll
            for (int mt = 0; mt < 2; mt++) {
                ldm_x4(ah[mt], a_addr(bb + S1_AH, wm * 32 + mt * 16, lane, koff));
                ldm_x4(al[mt], a_addr(bb + S1_AL, wm * 32 + mt * 16, lane, koff));
            }
#pragma unroll
            for (int p = 0; p < 2; p++) {
                ldm_x4(fh[p], b_addr(bb + S1_FH, wn * 32 + p * 16, lane, koff));
                ldm_x4(fl[p], b_addr(bb + S1_FL, wn * 32 + p * 16, lane, koff));
            }
#pragma unroll
            for (int mt = 0; mt < 2; mt++)
#pragma unroll
                for (int nt = 0; nt < 4; nt++) {
                    const uint32_t* bh = &fh[nt >> 1][(nt & 1) * 2];
                    const uint32_t* bl = &fl[nt >> 1][(nt & 1) * 2];
                    mma_bf16(acc[mt][nt], ah[mt], bh);
                    mma_bf16(acc[mt][nt], ah[mt], bl);
                    mma_bf16(acc[mt][nt], al[mt], bh);
                }
        }
        __syncthreads();
    }

    // Epilogue
    const bool isA = (m0 < NA);
#pragma unroll
    for (int mt = 0; mt < 2; mt++)
#pragma unroll
        for (int nt = 0; nt < 4; nt++)
#pragma unroll
            for (int h = 0; h < 2; h++) {
                const int grow = m0 + wm * 32 + mt * 16 + (lane >> 2) + h * 8;
                const int col  = n0 + wn * 32 + nt * 8 + (lane & 3) * 2;
                const float v0 = acc[mt][nt][h * 2 + 0];
                const float v1 = acc[mt][nt][h * 2 + 1];
                if (isA) {
                    const float p0 = fmaxf(v0, 0.0f), p1 = fmaxf(v1, 0.0f);
                    const __nv_bfloat16 h0 = __float2bfloat16(p0), h1 = __float2bfloat16(p1);
                    const __nv_bfloat16 l0 = __float2bfloat16(p0 - __bfloat162float(h0));
                    const __nv_bfloat16 l1 = __float2bfloat16(p1 - __bfloat162float(h1));
                    const size_t idx = (size_t)grow * KK + col;
                    *reinterpret_cast<__nv_bfloat162*>(g_Ph + idx) = __nv_bfloat162(h0, h1);
                    *reinterpret_cast<__nv_bfloat162*>(g_Pl + idx) = __nv_bfloat162(l0, l1);
                } else {
                    const size_t idx = (size_t)(grow - NA) * KK + col;
                    *reinterpret_cast<__nv_bfloat162*>(g_Mb + idx) = __nv_bfloat162(
                        __float2bfloat16(v0 <= 0.0f ? 1.0f : 0.0f),
                        __float2bfloat16(v1 <= 0.0f ? 1.0f : 0.0f));
                }
            }
}

// ---------------------------------------------------------------------------
// Stage 2: out[1024x1024] = P · M^T  (Ph·M + Pl·M), tile 128x128
// grid (8, 8), 256 threads, warp tile 32x64.
// ---------------------------------------------------------------------------
constexpr uint32_t S2_PH = 0;
constexpr uint32_t S2_PL = 10240;
constexpr uint32_t S2_MB = 20480;
constexpr uint32_t S2_BUF = 30720;
constexpr int S2_SMEM = 61440;

__global__ __launch_bounds__(256) void stage2_mma(float* __restrict__ out)
{
    extern __shared__ char dsm[];
    const uint32_t sb = smem_u32(dsm);

    const int tid = threadIdx.x;
    const int lane = tid & 31;
    const int wid = tid >> 5;
    const int wm = wid & 3;          // 4 warp rows x 32
    const int wn = wid >> 2;         // 2 warp cols x 64

    const int i0 = blockIdx.y * 128;
    const int j0 = blockIdx.x * 128;
    const __nv_bfloat16* Ph = g_Ph + (size_t)i0 * KK;
    const __nv_bfloat16* Pl = g_Pl + (size_t)i0 * KK;
    const __nv_bfloat16* Mb = g_Mb + (size_t)j0 * KK;

    float acc[2][8][4] = {};

    auto load_chunk = [&](int ch, uint32_t bb) {
        const int k0 = ch * 32;
        load_tile(bb + S2_PH, Ph, 128, KK, k0, tid);
        load_tile(bb + S2_PL, Pl, 128, KK, k0, tid);
        load_tile(bb + S2_MB, Mb, 128, KK, k0, tid);
        cp_commit();
    };

    constexpr int NCH = KK / 32;   // 8
    load_chunk(0, sb);
    for (int ch = 0; ch < NCH; ch++) {
        const bool more = (ch + 1 < NCH);
        if (more) load_chunk(ch + 1, sb + ((ch + 1) & 1) * S2_BUF);
        if (more) cp_wait1(); else cp_wait0();
        __syncthreads();

        const uint32_t bb = sb + (ch & 1) * S2_BUF;
#pragma unroll
        for (int ks = 0; ks < 2; ks++) {
            const int koff = ks * 32;
            uint32_t ph[2][4], pl[2][4], mb[4][4];
#pragma unroll
            for (int mt = 0; mt < 2; mt++) {
                ldm_x4(ph[mt], a_addr(bb + S2_PH, wm * 32 + mt * 16, lane, koff));
                ldm_x4(pl[mt], a_addr(bb + S2_PL, wm * 32 + mt * 16, lane, koff));
            }
#pragma unroll
            for (int p = 0; p < 4; p++)
                ldm_x4(mb[p], b_addr(bb + S2_MB, wn * 64 + p * 16, lane, koff));
#pragma unroll
            for (int mt = 0; mt < 2; mt++)
#pragma unroll
                for (int nt = 0; nt < 8; nt++) {
                    const uint32_t* bm = &mb[nt >> 1][(nt & 1) * 2];
                    mma_bf16(acc[mt][nt], ph[mt], bm);
                    mma_bf16(acc[mt][nt], pl[mt], bm);
                }
        }
        __syncthreads();
    }

#pragma unroll
    for (int mt = 0; mt < 2; mt++)
#pragma unroll
        for (int nt = 0; nt < 8; nt++)
#pragma unroll
            for (int h = 0; h < 2; h++) {
                const int row = i0 + wm * 32 + mt * 16 + (lane >> 2) + h * 8;
                const int col = j0 + wn * 64 + nt * 8 + (lane & 3) * 2;
                *reinterpret_cast<float2*>(out + (size_t)row * NB + col) =
                    make_float2(acc[mt][nt][h * 2 + 0], acc[mt][nt][h * 2 + 1]);
            }
}

// ---------------------------------------------------------------------------
extern "C" void kernel_launch(void* const* d_in, const int* in_sizes, int n_in,
                              void* d_out, int out_size)
{
    const float* a     = (const float*)d_in[0];
    const float* b     = (const float*)d_in[1];
    const float* feats = (const float*)d_in[2];
    float* out = (float*)d_out;
    (void)in_sizes; (void)n_in; (void)out_size;

    static bool attr_done = false;
    if (!attr_done) {
        cudaFuncSetAttribute(stage1_mma, cudaFuncAttributeMaxDynamicSharedMemorySize, S1_SMEM);
        cudaFuncSetAttribute(stage2_mma, cudaFuncAttributeMaxDynamicSharedMemorySize, S2_SMEM);
        attr_done = true;
    }

    convert_kernel<<<(XROWS * DD / 4 + KK * DD / 4 + 255) / 256, 256>>>(a, b, feats);
    stage1_mma<<<dim3(4, 16), 256, S1_SMEM>>>();
    stage2_mma<<<dim3(8, 8), 256, S2_SMEM>>>(out);
}

// round 4
// speedup vs baseline: 2.4374x; 1.5701x over previous
#include <cuda_runtime.h>
#include <cuda_bf16.h>
#include <cstdint>

constexpr int NA = 1024, NB = 1024, DD = 512, KK = 256;

// Device scratch
__device__ __nv_bfloat16 g_Ph[NA * KK];
__device__ __nv_bfloat16 g_Pl[NA * KK];
__device__ __nv_bfloat16 g_Mb[NB * KK];

// ---------------------------------------------------------------------------
// PTX helpers (sm_80+ family-safe)
// ---------------------------------------------------------------------------
__device__ __forceinline__ uint32_t smem_u32(const void* p) {
    uint32_t r;
    asm("{ .reg .u64 t; cvta.to.shared.u64 t, %1; cvt.u32.u64 %0, t; }" : "=r"(r) : "l"(p));
    return r;
}
__device__ __forceinline__ void cp16(uint32_t dst, const void* src) {
    asm volatile("cp.async.cg.shared.global [%0], [%1], 16;" :: "r"(dst), "l"(src) : "memory");
}
__device__ __forceinline__ void cp_commit() { asm volatile("cp.async.commit_group;" ::: "memory"); }
__device__ __forceinline__ void cp_wait1()  { asm volatile("cp.async.wait_group 1;" ::: "memory"); }
__device__ __forceinline__ void cp_wait0()  { asm volatile("cp.async.wait_group 0;" ::: "memory"); }

__device__ __forceinline__ void ldm_x4(uint32_t* r, uint32_t addr) {
    asm volatile("ldmatrix.sync.aligned.m8n8.x4.shared.b16 {%0,%1,%2,%3}, [%4];"
                 : "=r"(r[0]), "=r"(r[1]), "=r"(r[2]), "=r"(r[3]) : "r"(addr));
}
__device__ __forceinline__ void mma_bf16(float* d, const uint32_t* a, const uint32_t* b) {
    asm volatile(
        "mma.sync.aligned.m16n8k16.row.col.f32.bf16.bf16.f32 "
        "{%0,%1,%2,%3}, {%4,%5,%6,%7}, {%8,%9}, {%0,%1,%2,%3};"
        : "+f"(d[0]), "+f"(d[1]), "+f"(d[2]), "+f"(d[3])
        : "r"(a[0]), "r"(a[1]), "r"(a[2]), "r"(a[3]), "r"(b[0]), "r"(b[1]));
}

// smem tile geometry: k-chunk 32 bf16 per row = 64B data, padded to 80B rows
constexpr uint32_t RSTRIDE = 80;

__device__ __forceinline__ uint32_t a_addr(uint32_t base, int row0, int lane, int koff) {
    return base + (uint32_t)(row0 + (lane & 15)) * RSTRIDE + (uint32_t)koff + ((lane >> 4) << 4);
}
__device__ __forceinline__ uint32_t b_addr(uint32_t base, int row0, int lane, int koff) {
    return base + (uint32_t)(row0 + (lane & 7) + ((lane >> 4) << 3)) * RSTRIDE
                + (uint32_t)koff + (((lane >> 3) & 1) << 4);
}

// pack float4 -> (hi uint2, lo uint2) bf16 pairs
__device__ __forceinline__ void split_pack(const float4& v, uint2& h, uint2& l) {
    float xs[4] = {v.x, v.y, v.z, v.w};
    __nv_bfloat16 hs[4], ls[4];
#pragma unroll
    for (int i = 0; i < 4; i++) {
        hs[i] = __float2bfloat16(xs[i]);
        ls[i] = __float2bfloat16(xs[i] - __bfloat162float(hs[i]));
    }
    __nv_bfloat162 h01(hs[0], hs[1]), h23(hs[2], hs[3]);
    __nv_bfloat162 l01(ls[0], ls[1]), l23(ls[2], ls[3]);
    h.x = *reinterpret_cast<uint32_t*>(&h01); h.y = *reinterpret_cast<uint32_t*>(&h23);
    l.x = *reinterpret_cast<uint32_t*>(&l01); l.y = *reinterpret_cast<uint32_t*>(&l23);
}

// ---------------------------------------------------------------------------
// Stage 1 (fused convert): C[2048x256] = X · F^T  (AhFh + AhFl + AlFh)
// Tile 64(M) x 64(N), k-chunks of 32. grid (4, 32), 256 threads.
// fp32 loaded via LDG into registers, split to bf16 h/l on the STS path.
// ---------------------------------------------------------------------------
constexpr uint32_t S1_XH = 0;
constexpr uint32_t S1_XL = 5120;
constexpr uint32_t S1_FH = 10240;
constexpr uint32_t S1_FL = 15360;
constexpr uint32_t S1_BUF = 20480;
constexpr int S1_SMEM = 40960;   // < 48KB: no attribute call needed

__global__ __launch_bounds__(256) void stage1_mma(
    const float* __restrict__ a, const float* __restrict__ b, const float* __restrict__ feats)
{
    extern __shared__ char dsm[];
    const uint32_t sb = smem_u32(dsm);

    const int tid = threadIdx.x;
    const int lane = tid & 31;
    const int wid = tid >> 5;
    const int wm = wid & 1;          // 2 warp rows x 32
    const int wn = wid >> 1;         // 4 warp cols x 16

    const int m0 = blockIdx.y * 64;  // 0..2047
    const int n0 = blockIdx.x * 64;  // 0..255
    const bool isA = (m0 < NA);
    const float* __restrict__ Xf = (isA ? a + (size_t)m0 * DD
                                        : b + (size_t)(m0 - NA) * DD);
    const float* __restrict__ Ff = feats + (size_t)n0 * DD;

    // per-thread load geometry: 64 rows x 8 float4 per chunk; 2 float4/thread/array
    const int r0 = tid >> 3, s0 = tid & 7;          // element 0
    const int r1 = (tid + 256) >> 3, s1 = s0;       // element 1 (same s)

    float4 rx[2], rf[2];
    auto ldg_chunk = [&](int ch) {
        const int d0 = ch * 32;
        rx[0] = *reinterpret_cast<const float4*>(Xf + (size_t)r0 * DD + d0 + s0 * 4);
        rx[1] = *reinterpret_cast<const float4*>(Xf + (size_t)r1 * DD + d0 + s1 * 4);
        rf[0] = *reinterpret_cast<const float4*>(Ff + (size_t)r0 * DD + d0 + s0 * 4);
        rf[1] = *reinterpret_cast<const float4*>(Ff + (size_t)r1 * DD + d0 + s1 * 4);
    };
    auto sts_chunk = [&](uint32_t bb) {
        char* bp = dsm + (bb - sb);
        const uint32_t off0 = (uint32_t)r0 * RSTRIDE + (uint32_t)(s0 << 3);
        const uint32_t off1 = (uint32_t)r1 * RSTRIDE + (uint32_t)(s1 << 3);
        uint2 h, l;
        split_pack(rx[0], h, l);
        *reinterpret_cast<uint2*>(bp + S1_XH + off0) = h;
        *reinterpret_cast<uint2*>(bp + S1_XL + off0) = l;
        split_pack(rx[1], h, l);
        *reinterpret_cast<uint2*>(bp + S1_XH + off1) = h;
        *reinterpret_cast<uint2*>(bp + S1_XL + off1) = l;
        split_pack(rf[0], h, l);
        *reinterpret_cast<uint2*>(bp + S1_FH + off0) = h;
        *reinterpret_cast<uint2*>(bp + S1_FL + off0) = l;
        split_pack(rf[1], h, l);
        *reinterpret_cast<uint2*>(bp + S1_FH + off1) = h;
        *reinterpret_cast<uint2*>(bp + S1_FL + off1) = l;
    };

    float acc[2][2][4] = {};

    constexpr int NCH = DD / 32;   // 16
    ldg_chunk(0);
    sts_chunk(sb);
    __syncthreads();

    for (int ch = 0; ch < NCH; ch++) {
        const bool more = (ch + 1 < NCH);
        if (more) ldg_chunk(ch + 1);

        const uint32_t bb = sb + (uint32_t)(ch & 1) * S1_BUF;
#pragma unroll
        for (int ks = 0; ks < 2; ks++) {
            const int koff = ks * 32;
            uint32_t ah[2][4], al[2][4], fh[4], fl[4];
#pragma unroll
            for (int mt = 0; mt < 2; mt++) {
                ldm_x4(ah[mt], a_addr(bb + S1_XH, wm * 32 + mt * 16, lane, koff));
                ldm_x4(al[mt], a_addr(bb + S1_XL, wm * 32 + mt * 16, lane, koff));
            }
            ldm_x4(fh, b_addr(bb + S1_FH, wn * 16, lane, koff));
            ldm_x4(fl, b_addr(bb + S1_FL, wn * 16, lane, koff));
#pragma unroll
            for (int mt = 0; mt < 2; mt++)
#pragma unroll
                for (int nt = 0; nt < 2; nt++) {
                    mma_bf16(acc[mt][nt], ah[mt], &fh[nt * 2]);
                    mma_bf16(acc[mt][nt], ah[mt], &fl[nt * 2]);
                    mma_bf16(acc[mt][nt], al[mt], &fh[nt * 2]);
                }
        }
        __syncthreads();
        if (more) { sts_chunk(sb + (uint32_t)((ch + 1) & 1) * S1_BUF); __syncthreads(); }
    }

    // Epilogue
#pragma unroll
    for (int mt = 0; mt < 2; mt++)
#pragma unroll
        for (int nt = 0; nt < 2; nt++)
#pragma unroll
            for (int h = 0; h < 2; h++) {
                const int grow = m0 + wm * 32 + mt * 16 + (lane >> 2) + h * 8;
                const int col  = n0 + wn * 16 + nt * 8 + (lane & 3) * 2;
                const float v0 = acc[mt][nt][h * 2 + 0];
                const float v1 = acc[mt][nt][h * 2 + 1];
                if (isA) {
                    const float p0 = fmaxf(v0, 0.0f), p1 = fmaxf(v1, 0.0f);
                    const __nv_bfloat16 h0 = __float2bfloat16(p0), h1 = __float2bfloat16(p1);
                    const __nv_bfloat16 l0 = __float2bfloat16(p0 - __bfloat162float(h0));
                    const __nv_bfloat16 l1 = __float2bfloat16(p1 - __bfloat162float(h1));
                    const size_t idx = (size_t)grow * KK + col;
                    *reinterpret_cast<__nv_bfloat162*>(g_Ph + idx) = __nv_bfloat162(h0, h1);
                    *reinterpret_cast<__nv_bfloat162*>(g_Pl + idx) = __nv_bfloat162(l0, l1);
                } else {
                    const size_t idx = (size_t)(grow - NA) * KK + col;
                    *reinterpret_cast<__nv_bfloat162*>(g_Mb + idx) = __nv_bfloat162(
                        __float2bfloat16(v0 <= 0.0f ? 1.0f : 0.0f),
                        __float2bfloat16(v1 <= 0.0f ? 1.0f : 0.0f));
                }
            }
}

// ---------------------------------------------------------------------------
// Stage 2: out[1024x1024] = P · M^T  (Ph·M + Pl·M)
// Tile 64(M) x 128(N), k-chunks of 32. grid (8, 16), 256 threads, warp 32x32.
// ---------------------------------------------------------------------------
constexpr uint32_t S2_PH = 0;
constexpr uint32_t S2_PL = 5120;
constexpr uint32_t S2_MB = 10240;
constexpr uint32_t S2_BUF = 20480;
constexpr int S2_SMEM = 40960;

__device__ __forceinline__ void load_tile(uint32_t dst, const __nv_bfloat16* __restrict__ src,
                                          int rows, int ld, int d0, int tid)
{
    int n = rows * 4;   // 4 x 16B per row
    for (int v = tid; v < n; v += 256) {
        int r = v >> 2, s = v & 3;
        cp16(dst + (uint32_t)r * RSTRIDE + (uint32_t)(s << 4),
             src + (size_t)r * ld + d0 + s * 8);
    }
}

__global__ __launch_bounds__(256) void stage2_mma(float* __restrict__ out)
{
    extern __shared__ char dsm[];
    const uint32_t sb = smem_u32(dsm);

    const int tid = threadIdx.x;
    const int lane = tid & 31;
    const int wid = tid >> 5;
    const int wm = wid & 1;          // 2 warp rows x 32
    const int wn = wid >> 1;         // 4 warp cols x 32

    const int i0 = blockIdx.y * 64;
    const int j0 = blockIdx.x * 128;
    const __nv_bfloat16* Ph = g_Ph + (size_t)i0 * KK;
    const __nv_bfloat16* Pl = g_Pl + (size_t)i0 * KK;
    const __nv_bfloat16* Mb = g_Mb + (size_t)j0 * KK;

    float acc[2][4][4] = {};

    auto load_chunk = [&](int ch, uint32_t bb) {
        const int k0 = ch * 32;
        load_tile(bb + S2_PH, Ph,  64, KK, k0, tid);
        load_tile(bb + S2_PL, Pl,  64, KK, k0, tid);
        load_tile(bb + S2_MB, Mb, 128, KK, k0, tid);
        cp_commit();
    };

    constexpr int NCH = KK / 32;   // 8
    load_chunk(0, sb);
    for (int ch = 0; ch < NCH; ch++) {
        const bool more = (ch + 1 < NCH);
        if (more) load_chunk(ch + 1, sb + (uint32_t)((ch + 1) & 1) * S2_BUF);
        if (more) cp_wait1(); else cp_wait0();
        __syncthreads();

        const uint32_t bb = sb + (uint32_t)(ch & 1) * S2_BUF;
#pragma unroll
        for (int ks = 0; ks < 2; ks++) {
            const int koff = ks * 32;
            uint32_t ph[2][4], pl[2][4], mb[2][4];
#pragma unroll
            for (int mt = 0; mt < 2; mt++) {
                ldm_x4(ph[mt], a_addr(bb + S2_PH, wm * 32 + mt * 16, lane, koff));
                ldm_x4(pl[mt], a_addr(bb + S2_PL, wm * 32 + mt * 16, lane, koff));
            }
#pragma unroll
            for (int p = 0; p < 2; p++)
                ldm_x4(mb[p], b_addr(bb + S2_MB, wn * 32 + p * 16, lane, koff));
#pragma unroll
            for (int mt = 0; mt < 2; mt++)
#pragma unroll
                for (int nt = 0; nt < 4; nt++) {
                    const uint32_t* bm = &mb[nt >> 1][(nt & 1) * 2];
                    mma_bf16(acc[mt][nt], ph[mt], bm);
                    mma_bf16(acc[mt][nt], pl[mt], bm);
                }
        }
        __syncthreads();
    }

#pragma unroll
    for (int mt = 0; mt < 2; mt++)
#pragma unroll
        for (int nt = 0; nt < 4; nt++)
#pragma unroll
            for (int h = 0; h < 2; h++) {
                const int row = i0 + wm * 32 + mt * 16 + (lane >> 2) + h * 8;
                const int col = j0 + wn * 32 + nt * 8 + (lane & 3) * 2;
                *reinterpret_cast<float2*>(out + (size_t)row * NB + col) =
                    make_float2(acc[mt][nt][h * 2 + 0], acc[mt][nt][h * 2 + 1]);
            }
}

// ---------------------------------------------------------------------------
extern "C" void kernel_launch(void* const* d_in, const int* in_sizes, int n_in,
                              void* d_out, int out_size)
{
    const float* a     = (const float*)d_in[0];
    const float* b     = (const float*)d_in[1];
    const float* feats = (const float*)d_in[2];
    float* out = (float*)d_out;
    (void)in_sizes; (void)n_in; (void)out_size;

    stage1_mma<<<dim3(4, 32), 256, S1_SMEM>>>(a, b, feats);
    stage2_mma<<<dim3(8, 16), 256, S2_SMEM>>>(out);
}